// round 1
// baseline (speedup 1.0000x reference)
#include <cuda_runtime.h>
#include <cstdint>

#define NN      50000
#define NGRAPH  64
#define HID     128
#define NLAYERS 4

// ---------------- scratch (no allocations allowed) ----------------
__device__ float g_h[NN * HID];     // activations
__device__ float g_t[NN * HID];     // h @ W
__device__ float g_agg[NN * HID];   // aggregated messages
__device__ float g_deg[NN];
__device__ float g_dinv[NN];
__device__ float g_pooled[NGRAPH * HID];
__device__ int   g_idx64;           // 1 if index buffers are int64, 0 if int32

// ---------------- dtype detection -------------------------------
// If underlying data is little-endian int64 with values < 2^31, every odd
// 32-bit word is zero. Random int32 indices in [0, 50000) make that
// essentially impossible, so this is a safe discriminator.
__global__ void detect_dtype_kernel(const int* __restrict__ e) {
    int flag = 1;
    for (int i = 1; i < 2048; i += 2) {
        if (e[i] != 0) { flag = 0; break; }
    }
    g_idx64 = flag;
}

__device__ __forceinline__ int load_index(const void* p, long long i, int is64) {
    if (is64) return (int)(((const long long*)p)[i]);
    return ((const int*)p)[i];
}

// ---------------- degree / norm ----------------------------------
__global__ void deg_init_kernel(int n) {
    int i = blockIdx.x * blockDim.x + threadIdx.x;
    if (i < n) g_deg[i] = 1.0f;   // self-loop
}

__global__ void deg_accum_kernel(const void* __restrict__ eidx, int E) {
    int is64 = g_idx64;
    int i = blockIdx.x * blockDim.x + threadIdx.x;
    if (i < E) {
        int c = load_index(eidx, (long long)E + i, is64);  // target/col
        atomicAdd(&g_deg[c], 1.0f);
    }
}

__global__ void dinv_kernel(int n) {
    int i = blockIdx.x * blockDim.x + threadIdx.x;
    if (i < n) g_dinv[i] = rsqrtf(g_deg[i]);   // deg >= 1 always
}

// ---------------- GEMM: C[M,128] = A[M,128] @ W[128,128] (+bias, relu) ----
// BM=128, BN=128, BK=32. 256 threads (16x16), each computes 8x8.
__global__ __launch_bounds__(256) void gemm_kernel(
    const float* __restrict__ A, const float* __restrict__ W,
    const float* __restrict__ bias, float* __restrict__ C,
    int M, int do_relu)
{
    __shared__ float As[128 * 32];
    __shared__ float Bs[32 * 128];

    const int tid = threadIdx.x;
    const int ty = tid >> 4;        // 0..15
    const int tx = tid & 15;        // 0..15
    const int row0 = blockIdx.x * 128;

    float acc[8][8];
#pragma unroll
    for (int i = 0; i < 8; i++)
#pragma unroll
        for (int j = 0; j < 8; j++) acc[i][j] = 0.0f;

    for (int kc = 0; kc < 128; kc += 32) {
        // load A tile: 128x32 floats = 1024 float4, 4 per thread
#pragma unroll
        for (int l = 0; l < 4; l++) {
            int f = tid + l * 256;          // 0..1023
            int r = f >> 3;                 // row in tile
            int c4 = f & 7;                 // float4 column
            int grow = row0 + r;
            float4 v = make_float4(0.f, 0.f, 0.f, 0.f);
            if (grow < M)
                v = *(const float4*)&A[(size_t)grow * 128 + kc + c4 * 4];
            *(float4*)&As[r * 32 + c4 * 4] = v;
        }
        // load B tile: 32x128 floats = 1024 float4, 4 per thread
#pragma unroll
        for (int l = 0; l < 4; l++) {
            int f = tid + l * 256;
            int r = f >> 5;                 // 0..31
            int c4 = f & 31;
            *(float4*)&Bs[r * 128 + c4 * 4] =
                *(const float4*)&W[(size_t)(kc + r) * 128 + c4 * 4];
        }
        __syncthreads();

#pragma unroll
        for (int k = 0; k < 32; k++) {
            float a[8], b[8];
#pragma unroll
            for (int i = 0; i < 8; i++) a[i] = As[(ty * 8 + i) * 32 + k];
            *(float4*)&b[0] = *(float4*)&Bs[k * 128 + tx * 8];
            *(float4*)&b[4] = *(float4*)&Bs[k * 128 + tx * 8 + 4];
#pragma unroll
            for (int i = 0; i < 8; i++)
#pragma unroll
                for (int j = 0; j < 8; j++)
                    acc[i][j] = fmaf(a[i], b[j], acc[i][j]);
        }
        __syncthreads();
    }

    // epilogue
    float bv[8];
#pragma unroll
    for (int j = 0; j < 8; j++) bv[j] = bias ? bias[tx * 8 + j] : 0.0f;

#pragma unroll
    for (int i = 0; i < 8; i++) {
        int grow = row0 + ty * 8 + i;
        if (grow < M) {
            float r[8];
#pragma unroll
            for (int j = 0; j < 8; j++) {
                float v = acc[i][j] + bv[j];
                r[j] = do_relu ? fmaxf(v, 0.0f) : v;
            }
            *(float4*)&C[(size_t)grow * 128 + tx * 8]     = *(float4*)&r[0];
            *(float4*)&C[(size_t)grow * 128 + tx * 8 + 4] = *(float4*)&r[4];
        }
    }
}

// ---------------- self-loop init: agg[n] = t[n] * dinv[n]^2 --------------
__global__ void selfloop_init_kernel(int n) {
    int i = blockIdx.x * blockDim.x + threadIdx.x;   // float4 index
    int total = n * (HID / 4);
    if (i < total) {
        int node = i >> 5;                            // HID/4 = 32 float4/row
        float d = g_dinv[node];
        float s = d * d;
        float4 v = ((const float4*)g_t)[i];
        v.x *= s; v.y *= s; v.z *= s; v.w *= s;
        ((float4*)g_agg)[i] = v;
    }
}

// ---------------- edge scatter: one warp per edge ------------------------
__global__ __launch_bounds__(256) void scatter_kernel(const void* __restrict__ eidx, int E) {
    const int is64 = g_idx64;
    const int lane = threadIdx.x & 31;
    int w = (blockIdx.x * blockDim.x + threadIdx.x) >> 5;
    const int nw = (gridDim.x * blockDim.x) >> 5;

    for (int e = w; e < E; e += nw) {
        int s, t;
        if (is64) {
            s = (int)((const long long*)eidx)[e];
            t = (int)((const long long*)eidx)[(long long)E + e];
        } else {
            s = ((const int*)eidx)[e];
            t = ((const int*)eidx)[E + e];
        }
        float nrm = g_dinv[s] * g_dinv[t];
        float4 v = ((const float4*)(g_t + (size_t)s * HID))[lane];
        float* dst = g_agg + (size_t)t * HID + lane * 4;
        asm volatile(
            "red.global.add.v4.f32 [%0], {%1, %2, %3, %4};"
            :: "l"(dst), "f"(v.x * nrm), "f"(v.y * nrm),
               "f"(v.z * nrm), "f"(v.w * nrm)
            : "memory");
    }
}

// ---------------- h = relu(agg + b) --------------------------------------
__global__ void relu_bias_kernel(const float* __restrict__ bias, int n) {
    int i = blockIdx.x * blockDim.x + threadIdx.x;   // float4 index
    int total = n * (HID / 4);
    if (i < total) {
        float4 v = ((const float4*)g_agg)[i];
        float4 b = ((const float4*)bias)[i & 31];
        v.x = fmaxf(v.x + b.x, 0.0f);
        v.y = fmaxf(v.y + b.y, 0.0f);
        v.z = fmaxf(v.z + b.z, 0.0f);
        v.w = fmaxf(v.w + b.w, 0.0f);
        ((float4*)g_h)[i] = v;
    }
}

// ---------------- mean pool per graph (batch is sorted) ------------------
__device__ __forceinline__ int lower_bound_batch(const void* batch, int n, int val, int is64) {
    int lo = 0, hi = n;
    while (lo < hi) {
        int mid = (lo + hi) >> 1;
        long long b = is64 ? ((const long long*)batch)[mid]
                           : (long long)((const int*)batch)[mid];
        if (b < val) lo = mid + 1; else hi = mid;
    }
    return lo;
}

__global__ void pool_kernel(const void* __restrict__ batch, int n) {
    const int g = blockIdx.x;
    const int tid = threadIdx.x;
    __shared__ int slo, shi;
    if (tid == 0) {
        int is64 = g_idx64;
        slo = lower_bound_batch(batch, n, g, is64);
        shi = lower_bound_batch(batch, n, g + 1, is64);
    }
    __syncthreads();
    float sum = 0.0f;
    for (int r = slo; r < shi; r++)
        sum += g_h[(size_t)r * HID + tid];
    float cnt = (float)(shi - slo);
    g_pooled[g * HID + tid] = sum / fmaxf(cnt, 1.0f);
}

// ---------------- heads: out[head][g][:] = pooled[g] @ W_head + b_head ---
__global__ void heads_kernel(
    const float* __restrict__ Wd, const float* __restrict__ bd,
    const float* __restrict__ Ws, const float* __restrict__ bsn,
    const float* __restrict__ Wr, const float* __restrict__ br,
    float* __restrict__ out)
{
    const int g = blockIdx.x;
    const int head = blockIdx.y;
    const int j = threadIdx.x;
    __shared__ float p[HID];
    p[j] = g_pooled[g * HID + j];
    __syncthreads();

    const float* W = (head == 0) ? Wd : (head == 1) ? Ws : Wr;
    const float* b = (head == 0) ? bd : (head == 1) ? bsn : br;
    float s = b[j];
#pragma unroll 8
    for (int k = 0; k < HID; k++)
        s = fmaf(p[k], W[k * HID + j], s);
    out[(size_t)head * NGRAPH * HID + g * HID + j] = s;
}

// ---------------- launch --------------------------------------------------
extern "C" void kernel_launch(void* const* d_in, const int* in_sizes, int n_in,
                              void* d_out, int out_size)
{
    const float* x      = (const float*)d_in[0];
    const void*  eidx   = d_in[1];
    const void*  batch  = d_in[2];
    const float* W_in   = (const float*)d_in[3];
    const float* b_in   = (const float*)d_in[4];
    const float* conv_W = (const float*)d_in[5];
    const float* conv_b = (const float*)d_in[6];
    const float* W_def  = (const float*)d_in[7];
    const float* b_def  = (const float*)d_in[8];
    const float* W_syn  = (const float*)d_in[9];
    const float* b_syn  = (const float*)d_in[10];
    const float* W_rel  = (const float*)d_in[11];
    const float* b_rel  = (const float*)d_in[12];
    float* out = (float*)d_out;

    const int N = in_sizes[0] / HID;       // 50000
    const int E = in_sizes[1] / 2;         // 640000

    // scratch pointers from device symbols (no allocation)
    void *ph, *pt;
    cudaGetSymbolAddress(&ph, g_h);
    cudaGetSymbolAddress(&pt, g_t);
    float* h_buf = (float*)ph;
    float* t_buf = (float*)pt;

    const int T = 256;
    const int nv4 = N * (HID / 4);

    // 0. index dtype detection (writes g_idx64, read by later kernels)
    detect_dtype_kernel<<<1, 1>>>((const int*)eidx);

    // 1. gcn_norm: degrees + dinv
    deg_init_kernel<<<(N + T - 1) / T, T>>>(N);
    deg_accum_kernel<<<(E + T - 1) / T, T>>>(eidx, E);
    dinv_kernel<<<(N + T - 1) / T, T>>>(N);

    // 2. input layer: h = relu(x @ W_in + b_in)
    gemm_kernel<<<(N + 127) / 128, 256>>>(x, W_in, b_in, h_buf, N, 1);

    // 3. GCN layers
    for (int l = 0; l < NLAYERS; l++) {
        gemm_kernel<<<(N + 127) / 128, 256>>>(
            h_buf, conv_W + (size_t)l * HID * HID, nullptr, t_buf, N, 0);
        selfloop_init_kernel<<<(nv4 + T - 1) / T, T>>>(N);
        scatter_kernel<<<4096, 256>>>(eidx, E);
        relu_bias_kernel<<<(nv4 + T - 1) / T, T>>>(conv_b + (size_t)l * HID, N);
    }

    // 4. global mean pool
    pool_kernel<<<NGRAPH, HID>>>(batch, N);

    // 5. output heads
    heads_kernel<<<dim3(NGRAPH, 3), HID>>>(W_def, b_def, W_syn, b_syn,
                                           W_rel, b_rel, out);
}